// round 14
// baseline (speedup 1.0000x reference)
#include <cuda_runtime.h>
#include <cuda_fp16.h>
#include <cstdint>

#define SDIM 2048
#define HEADS 16
#define HDIM 64
#define BM 64
#define BN 128
#define NTILE (SDIM / BN)
#define RSTR 72        // halfs per padded row
#define ROWB 144       // bytes per padded row
#define PLANE 18432    // 128 rows * 144 B : one plane of one tile
#define BUFB 55296     // 3 planes (KH,KL,VH)
#define NSTAGE 2
#define ONES2 0x3C003C00u   // half2(1.0, 1.0)

__device__ __half g_KH[(size_t)2 * HEADS * SDIM * RSTR];
__device__ __half g_KL[(size_t)2 * HEADS * SDIM * RSTR];
__device__ __half g_VH[(size_t)2 * HEADS * SDIM * RSTR];
__device__ int g_mask_word_mode;

__device__ __forceinline__ uint32_t pack_h2(float x, float y) {
    __half2 h = __floats2half2_rn(x, y);
    return *reinterpret_cast<uint32_t*>(&h);
}
__device__ __forceinline__ void split_h2(float x, float y, uint32_t& hi, uint32_t& lo) {
    const __half hx = __float2half_rn(x), hy = __float2half_rn(y);
    __half2 hp = __halves2half2(hx, hy);
    hi = *reinterpret_cast<uint32_t*>(&hp);
    lo = pack_h2(x - __half2float(hx), y - __half2float(hy));
}
__device__ __forceinline__ uint32_t cvt_h2(float lo, float hi) {
    uint32_t d; asm("cvt.rn.f16x2.f32 %0, %1, %2;" : "=r"(d) : "f"(hi), "f"(lo)); return d;
}
__device__ __forceinline__ float ex2f(float x) {
    float r; asm("ex2.approx.f32 %0, %1;" : "=f"(r) : "f"(x)); return r;
}
__device__ __forceinline__ void mma16816(float* c, const uint32_t* a, uint32_t b0, uint32_t b1) {
    asm volatile(
        "mma.sync.aligned.m16n8k16.row.col.f32.f16.f16.f32 "
        "{%0,%1,%2,%3}, {%4,%5,%6,%7}, {%8,%9}, {%0,%1,%2,%3};"
        : "+f"(c[0]), "+f"(c[1]), "+f"(c[2]), "+f"(c[3])
        : "r"(a[0]), "r"(a[1]), "r"(a[2]), "r"(a[3]), "r"(b0), "r"(b1));
}
__device__ __forceinline__ void ldsm4(uint32_t& a, uint32_t& b, uint32_t& c, uint32_t& d, uint32_t addr) {
    asm volatile("ldmatrix.sync.aligned.m8n8.x4.shared.b16 {%0,%1,%2,%3}, [%4];"
                 : "=r"(a), "=r"(b), "=r"(c), "=r"(d) : "r"(addr));
}
__device__ __forceinline__ void ldsm4t(uint32_t& a, uint32_t& b, uint32_t& c, uint32_t& d, uint32_t addr) {
    asm volatile("ldmatrix.sync.aligned.m8n8.x4.trans.shared.b16 {%0,%1,%2,%3}, [%4];"
                 : "=r"(a), "=r"(b), "=r"(c), "=r"(d) : "r"(addr));
}
__device__ __forceinline__ void cpa16(uint32_t dst, const void* src) {
    asm volatile("cp.async.cg.shared.global [%0], [%1], 16;" :: "r"(dst), "l"(src));
}

// ---- one-shot K (hi/lo) + V (hi) prepack; block 0 warp 0 also does mask detect ----
__global__ __launch_bounds__(256)
void prepack_kernel(const float* __restrict__ kg, const float* __restrict__ vg,
                    const unsigned int* __restrict__ maskw) {
    const int idx = blockIdx.x * 256 + threadIdx.x;   // B*S*H*16 quads
    const int d4q = idx & 15;
    const int h   = (idx >> 4) & 15;
    const int s   = (idx >> 8) & 2047;
    const int b   = idx >> 19;
    const size_t src = (((size_t)b * SDIM + s) * HEADS + h) * HDIM + d4q * 4;
    const size_t dst = ((size_t)(b * HEADS + h) * SDIM + s) * RSTR + d4q * 4;
    uint32_t h01, l01, h23, l23;
    const float4 kx = *(const float4*)(kg + src);
    split_h2(kx.x, kx.y, h01, l01); split_h2(kx.z, kx.w, h23, l23);
    *(uint32_t*)&g_KH[dst] = h01; *(uint32_t*)&g_KH[dst + 2] = h23;
    *(uint32_t*)&g_KL[dst] = l01; *(uint32_t*)&g_KL[dst + 2] = l23;
    const float4 vx = *(const float4*)(vg + src);
    *(uint32_t*)&g_VH[dst]     = pack_h2(vx.x, vx.y);
    *(uint32_t*)&g_VH[dst + 2] = pack_h2(vx.z, vx.w);

    if (blockIdx.x == 0 && threadIdx.x < 32) {
        int bad = 0;
        #pragma unroll 8
        for (int i = threadIdx.x; i < 1024; i += 32) {
            const unsigned int w = maskw[i];
            bad |= (w != 0u && w != 1u && w != 0x3F800000u) ? 1 : 0;
        }
        const unsigned int any = __ballot_sync(0xffffffffu, bad);
        if (threadIdx.x == 0) g_mask_word_mode = (any == 0u) ? 1 : 0;
    }
}

__global__ __launch_bounds__(128, 2)
void attn_kernel(const float* __restrict__ qg, const float* __restrict__ biasg,
                 const unsigned char* __restrict__ maskg, float* __restrict__ outg)
{
    extern __shared__ char smem[];
    const uint32_t sbase = (uint32_t)__cvta_generic_to_shared(smem);
    const int tid = threadIdx.x, warp = tid >> 5, lane = tid & 31;
    const int q4 = lane & 3, r8 = lane >> 2;
    const int m0 = blockIdx.x * BM, h = blockIdx.y, b = blockIdx.z;
    const int row0 = m0 + warp * 16 + r8, row1 = row0 + 8;
    const int wordm = g_mask_word_mode;
    const int bh = b * HEADS + h;

    const int tl = lane >> 3, rr = lane & 7;
    // K (non-trans x4): tiles 0,1 = KH k-halves; tiles 2,3 = KL k-halves
    const uint32_t koff = (uint32_t)((tl >> 1) * PLANE + (tl & 1) * 16 + rr * ROWB);
    // V (trans x4): tiles 0,1 = key-halves of d-octet dnp*2; tiles 2,3 = of dnp*2+1
    const uint32_t voff = (uint32_t)(2 * PLANE + ((tl & 1) * 8 + rr) * ROWB + (tl >> 1) * 16);

    // cp.async chunk coords (128 threads: 24 chunks of 16B each)
    const int ccol = tid & 7, crb = tid >> 3;   // crb in 0..15

    // ---- Q fragments, scaled by 8*log2(e), fp16 hi/lo split ----
    const float QSC = 8.0f * 1.44269504088896341f;
    uint32_t qh[4][4], ql[4][4];
    {
        const size_t qb0 = (((size_t)b * SDIM + row0) * HEADS + h) * HDIM;
        const size_t qb1 = (((size_t)b * SDIM + row1) * HEADS + h) * HDIM;
        #pragma unroll
        for (int dk = 0; dk < 4; dk++) {
            const int c0 = dk * 16 + 2 * q4;
            const float2 x00 = *(const float2*)(qg + qb0 + c0);
            const float2 x10 = *(const float2*)(qg + qb1 + c0);
            const float2 x01 = *(const float2*)(qg + qb0 + c0 + 8);
            const float2 x11 = *(const float2*)(qg + qb1 + c0 + 8);
            split_h2(QSC * x00.x, QSC * x00.y, qh[dk][0], ql[dk][0]);
            split_h2(QSC * x10.x, QSC * x10.y, qh[dk][1], ql[dk][1]);
            split_h2(QSC * x01.x, QSC * x01.y, qh[dk][2], ql[dk][2]);
            split_h2(QSC * x11.x, QSC * x11.y, qh[dk][3], ql[dk][3]);
        }
    }

    float o[8][4];
    #pragma unroll
    for (int i = 0; i < 8; i++) { o[i][0] = o[i][1] = o[i][2] = o[i][3] = 0.f; }
    float mro0 = -1e30f, mro1 = -1e30f, lro0 = 0.f, lro1 = 0.f;

    const size_t biasb0 = (((size_t)b * HEADS + h) * SDIM + row0) * SDIM;
    const size_t biasb1 = (((size_t)b * HEADS + h) * SDIM + row1) * SDIM;
    const size_t maskb0 = ((size_t)b * SDIM + row0) * SDIM;
    const size_t maskb1 = ((size_t)b * SDIM + row1) * SDIM;

    // ---- async tile prefetch: 3 planes x 128 rows x 128B, 24 chunks/thread ----
    #define PREFETCH(T, BUFI) do {                                              \
        const uint32_t dstb_ = sbase + (uint32_t)(BUFI) * BUFB;                 \
        const size_t rowbase_ = (size_t)bh * SDIM + (T) * BN;                   \
        _Pragma("unroll")                                                       \
        for (int i_ = 0; i_ < 24; i_++) {                                       \
            const int plane_ = i_ >> 3;                                         \
            const int r_ = (i_ & 7) * 16 + crb;                                 \
            const size_t so_ = (rowbase_ + r_) * RSTR + ccol * 8;               \
            const __half* sp_ = (plane_ == 0) ? (g_KH + so_)                    \
                              : (plane_ == 1) ? (g_KL + so_) : (g_VH + so_);    \
            cpa16(dstb_ + plane_ * PLANE + r_ * ROWB + ccol * 16, sp_);         \
        }                                                                       \
        asm volatile("cp.async.commit_group;" ::: "memory");                    \
    } while (0)

    PREFETCH(0, 0);

    for (int t = 0; t < NTILE; t++) {
        asm volatile("cp.async.wait_group 0;" ::: "memory");
        __syncthreads();   // tile t ready; all warps done reading buffer (t+1)&1
        if (t + 1 < NTILE) PREFETCH(t + 1, (t + 1) & 1);

        const uint32_t kb = sbase + (uint32_t)(t & 1) * BUFB;
        const int n0 = t * BN;

        float c[16][4];
        const float L2E = 1.44269504088896341f;

        // ---- two sub-blocks of 8 n-tiles: load bias/mask, QK 3-pass, apply ----
        #pragma unroll
        for (int sub = 0; sub < 2; sub++) {
            float2 bb0a[8], bb1a[8];
            int2   m0a[8], m1a[8];
            #pragma unroll
            for (int j = 0; j < 8; j++) {
                const int col = n0 + (sub * 8 + j) * 8 + 2 * q4;
                bb0a[j] = *(const float2*)(biasg + biasb0 + col);
                bb1a[j] = *(const float2*)(biasg + biasb1 + col);
                if (wordm) {
                    m0a[j] = *(const int2*)((const int*)maskg + maskb0 + col);
                    m1a[j] = *(const int2*)((const int*)maskg + maskb1 + col);
                } else {
                    m0a[j].x = *(const unsigned short*)(maskg + maskb0 + col);
                    m1a[j].x = *(const unsigned short*)(maskg + maskb1 + col);
                    m0a[j].y = 0; m1a[j].y = 0;
                }
            }
            #pragma unroll
            for (int j = 0; j < 8; j++) {
                const int nt = sub * 8 + j;
                c[nt][0] = c[nt][1] = c[nt][2] = c[nt][3] = 0.f;
            }
            #pragma unroll
            for (int dk = 0; dk < 4; dk++) {
                #pragma unroll
                for (int j = 0; j < 8; j++) {
                    const int nt = sub * 8 + j;
                    uint32_t bh0, bh1, bl0, bl1;
                    ldsm4(bh0, bh1, bl0, bl1, kb + koff + (uint32_t)(nt * 1152 + dk * 32));
                    mma16816(c[nt], qh[dk], bh0, bh1);
                    mma16816(c[nt], qh[dk], bl0, bl1);
                    mma16816(c[nt], ql[dk], bh0, bh1);
                }
            }
            #pragma unroll
            for (int j = 0; j < 8; j++) {
                const int nt = sub * 8 + j;
                int k00, k01, k10, k11;
                if (wordm) {
                    k00 = (m0a[j].x != 0); k01 = (m0a[j].y != 0);
                    k10 = (m1a[j].x != 0); k11 = (m1a[j].y != 0);
                } else {
                    k00 = (m0a[j].x & 0xff) != 0; k01 = ((m0a[j].x >> 8) & 0xff) != 0;
                    k10 = (m1a[j].x & 0xff) != 0; k11 = ((m1a[j].x >> 8) & 0xff) != 0;
                }
                c[nt][0] = k00 ? 0.f : fmaf(bb0a[j].x, L2E, c[nt][0]);
                c[nt][1] = k01 ? 0.f : fmaf(bb0a[j].y, L2E, c[nt][1]);
                c[nt][2] = k10 ? 0.f : fmaf(bb1a[j].x, L2E, c[nt][2]);
                c[nt][3] = k11 ? 0.f : fmaf(bb1a[j].y, L2E, c[nt][3]);
            }
        }

        // ---- online softmax in log2 domain over 128 columns ----
        float mx0 = -1e30f, mx1 = -1e30f;
        #pragma unroll
        for (int nt = 0; nt < 16; nt++) {
            mx0 = fmaxf(mx0, fmaxf(c[nt][0], c[nt][1]));
            mx1 = fmaxf(mx1, fmaxf(c[nt][2], c[nt][3]));
        }
        mx0 = fmaxf(mx0, __shfl_xor_sync(0xffffffffu, mx0, 1));
        mx0 = fmaxf(mx0, __shfl_xor_sync(0xffffffffu, mx0, 2));
        mx1 = fmaxf(mx1, __shfl_xor_sync(0xffffffffu, mx1, 1));
        mx1 = fmaxf(mx1, __shfl_xor_sync(0xffffffffu, mx1, 2));
        const float mn0 = fmaxf(mro0, mx0), mn1 = fmaxf(mro1, mx1);
        const float corr0 = ex2f(mro0 - mn0), corr1 = ex2f(mro1 - mn1);
        mro0 = mn0; mro1 = mn1;
        #pragma unroll
        for (int dn = 0; dn < 8; dn++) {
            o[dn][0] *= corr0; o[dn][1] *= corr0;
            o[dn][2] *= corr1; o[dn][3] *= corr1;
        }

        // ---- probs: ex2 then f16x2 pack into A-layout fragments (8 k-groups) ----
        uint32_t ph[8][4];
        #pragma unroll
        for (int nt = 0; nt < 16; nt++) {
            const float p0 = ex2f(c[nt][0] - mn0), p1 = ex2f(c[nt][1] - mn0);
            const float p2 = ex2f(c[nt][2] - mn1), p3 = ex2f(c[nt][3] - mn1);
            ph[nt >> 1][(nt & 1) * 2 + 0] = cvt_h2(p0, p1);
            ph[nt >> 1][(nt & 1) * 2 + 1] = cvt_h2(p2, p3);
        }

        // ---- row sums via ones-B MMA ----
        float csum[4] = {0.f, 0.f, 0.f, 0.f};
        #pragma unroll
        for (int kt = 0; kt < 8; kt++)
            mma16816(csum, ph[kt], ONES2, ONES2);

        // ---- P.V : single-pass; one ldsm4t feeds TWO d-octets ----
        #pragma unroll
        for (int kt = 0; kt < 8; kt++) {
            #pragma unroll
            for (int dnp = 0; dnp < 4; dnp++) {
                uint32_t v0, v1, v2, v3;
                ldsm4t(v0, v1, v2, v3, kb + voff + (uint32_t)(kt * 2304 + dnp * 32));
                mma16816(o[2 * dnp],     ph[kt], v0, v1);
                mma16816(o[2 * dnp + 1], ph[kt], v2, v3);
            }
        }

        lro0 = lro0 * corr0 + csum[0];
        lro1 = lro1 * corr1 + csum[2];
    }

    // ---- epilogue ----
    const float inv0 = 1.f / lro0, inv1 = 1.f / lro1;
    const size_t ob0 = ((size_t)b * SDIM + row0) * (HEADS * HDIM) + h * HDIM;
    const size_t ob1 = ((size_t)b * SDIM + row1) * (HEADS * HDIM) + h * HDIM;
    #pragma unroll
    for (int dn = 0; dn < 8; dn++) {
        float2 r0, r1;
        r0.x = o[dn][0] * inv0; r0.y = o[dn][1] * inv0;
        r1.x = o[dn][2] * inv1; r1.y = o[dn][3] * inv1;
        *(float2*)(outg + ob0 + dn * 8 + 2 * q4) = r0;
        *(float2*)(outg + ob1 + dn * 8 + 2 * q4) = r1;
    }
}

extern "C" void kernel_launch(void* const* d_in, const int* in_sizes, int n_in,
                              void* d_out, int out_size) {
    const float*         q    = (const float*)d_in[0];
    const float*         k    = (const float*)d_in[1];
    const float*         v    = (const float*)d_in[2];
    const float*         bias = (const float*)d_in[3];
    const unsigned char* mask = (const unsigned char*)d_in[4];
    float* out = (float*)d_out;

    prepack_kernel<<<4096, 256>>>(k, v, (const unsigned int*)mask);

    cudaFuncSetAttribute(attn_kernel, cudaFuncAttributeMaxDynamicSharedMemorySize, NSTAGE * BUFB);
    dim3 grid(SDIM / BM, HEADS, 2);
    attn_kernel<<<grid, 128, NSTAGE * BUFB>>>(q, bias, mask, out);
}